// round 1
// baseline (speedup 1.0000x reference)
#include <cuda_runtime.h>
#include <cstdint>

typedef unsigned long long u64;

// ---- packed fp32x2 helpers (sm_103a) ----
__device__ __forceinline__ u64 ffma2(u64 a, u64 b, u64 c) {
    u64 d;
    asm("fma.rn.f32x2 %0, %1, %2, %3;" : "=l"(d) : "l"(a), "l"(b), "l"(c));
    return d;
}
__device__ __forceinline__ u64 pack2(float x, float y) {
    u64 r; asm("mov.b64 %0, {%1, %2};" : "=l"(r) : "f"(x), "f"(y)); return r;
}
__device__ __forceinline__ float2 unpack2(u64 v) {
    float2 r; asm("mov.b64 {%0, %1}, %2;" : "=f"(r.x), "=f"(r.y) : "l"(v)); return r;
}
__device__ __forceinline__ float clip1(float v) { return fminf(fmaxf(v, -1.0f), 1.0f); }

constexpr int B_THREADS = 256;
constexpr int WARPS = B_THREADS / 32;
constexpr int GRID_BLOCKS = 592;   // 4 * 148 SMs

__global__ __launch_bounds__(B_THREADS, 2)
void lila_kernel(const float* __restrict__ inp,
                 const float* __restrict__ W1, const float* __restrict__ b1,
                 const float* __restrict__ W2, const float* __restrict__ b2,
                 const float* __restrict__ W3, const float* __restrict__ b3,
                 const float* __restrict__ E1, const float* __restrict__ c1,
                 const float* __restrict__ E2, const float* __restrict__ c2,
                 const float* __restrict__ E3, const float* __restrict__ c3,
                 float* __restrict__ out, int B)
{
    // per-warp workspaces
    __shared__ __align__(16) float gs_all[WARPS][512];   // 8x8 cells x 8 (6 used)
    __shared__ __align__(16) float h1_all[WARPS][288];   // 36 x 8
    __shared__ __align__(16) float h2_all[WARPS][288];   // 36 x 8
    __shared__ __align__(16) float vis_all[WARPS][40];   // 36 v + center + pad
    __shared__ __align__(16) float g1_all[WARPS][16];
    // shared (block) head weights, transposed + padded for conflict-free LDS
    __shared__ __align__(16) float E1T[16 * 38];         // [k][j], j<37 real
    __shared__ __align__(16) float E2T[16 * 18];         // [k][j], j<16 real
    __shared__ __align__(16) float E3s[16];
    __shared__ __align__(16) float c1s[16];
    __shared__ __align__(16) float c2s[16];
    __shared__ float c3s;

    const int tid = threadIdx.x;

    // --- stage head weights (transpose) ---
    for (int i = tid; i < 16 * 38; i += B_THREADS) {
        int k = i / 38, j = i - 38 * k;
        E1T[i] = (j < 37) ? E1[j * 16 + k] : 0.0f;
    }
    for (int i = tid; i < 16 * 18; i += B_THREADS) {
        int k = i / 18, j = i - 18 * k;
        E2T[i] = (j < 16) ? E2[j * 16 + k] : 0.0f;
    }
    if (tid < 16) { E3s[tid] = E3[tid]; c1s[tid] = c1[tid]; c2s[tid] = c2[tid]; }
    if (tid == 0) c3s = c3[0];

    const int lane = tid & 31;
    const int warp = tid >> 5;
    const int o    = lane & 7;   // output channel this lane owns (layers 1,2)
    const int slot = lane >> 3;  // patch slot 0..3

    // --- per-thread packed weights (columns) ---
    u64 w1p[27];
#pragma unroll
    for (int j = 0; j < 27; j++)
        w1p[j] = pack2(W1[(2 * j) * 8 + o], W1[(2 * j + 1) * 8 + o]);
    const float b1o = b1[o];
    u64 w2p[4];
#pragma unroll
    for (int j = 0; j < 4; j++)
        w2p[j] = pack2(W2[(2 * j) * 8 + o], W2[(2 * j + 1) * 8 + o]);
    const float b2o = b2[o];
    u64 w3p[4];
#pragma unroll
    for (int j = 0; j < 4; j++)
        w3p[j] = pack2(W3[2 * j], W3[2 * j + 1]);
    const float b3o = b3[0];

    float* gs   = gs_all[warp];
    float* h1s  = h1_all[warp];
    float* h2s  = h2_all[warp];
    float* viss = vis_all[warp];
    float* g1s  = g1_all[warp];
    if (lane == 0) { viss[37] = 0.0f; viss[38] = 0.0f; viss[39] = 0.0f; }
    __syncthreads();

    const int warpG = blockIdx.x * WARPS + warp;
    const int warpN = gridDim.x * WARPS;

    for (int row = warpG; row < B; row += warpN) {
        __syncwarp();  // protect viss/gs against previous iteration's readers
        const float* rp = inp + (size_t)row * 385;

        // --- stage 8x8x6 grid into padded SMEM cells ---
#pragma unroll
        for (int k2 = 0; k2 < 12; k2++) {
            int i = lane + 32 * k2;          // 0..383
            int cell = i / 6, f = i - 6 * cell;
            gs[cell * 8 + f] = __ldg(rp + i);
        }
        if (lane == 0) viss[36] = __ldg(rp + 384);
        __syncwarp();

        // --- layer 1: 36 patches x (54 -> 8), lane = (slot, o) ---
#pragma unroll 1
        for (int it = 0; it < 9; it++) {
            int p = it * 4 + slot;           // 0..35
            int x = p / 6, y = p - 6 * x;
            u64 a0 = 0ull, a1 = 0ull, a2 = 0ull;
#pragma unroll
            for (int c = 0; c < 9; c++) {
                int ox = c / 3, oy = c - 3 * (c / 3);
                const float* cp = gs + (((x + ox) << 3) + (y + oy)) * 8;
                ulonglong2 q = *reinterpret_cast<const ulonglong2*>(cp);
                u64 p45 = *reinterpret_cast<const u64*>(cp + 4);
                a0 = ffma2(q.x, w1p[c * 3 + 0], a0);
                a1 = ffma2(q.y, w1p[c * 3 + 1], a1);
                a2 = ffma2(p45, w1p[c * 3 + 2], a2);
            }
            float2 f0 = unpack2(a0), f1 = unpack2(a1), f2 = unpack2(a2);
            float h = ((f0.x + f0.y) + (f1.x + f1.y)) + ((f2.x + f2.y) + b1o);
            h1s[p * 8 + o] = clip1(h);
        }
        __syncwarp();

        // --- layer 2: 36 x (8 -> 8) ---
#pragma unroll 1
        for (int it = 0; it < 9; it++) {
            int p = it * 4 + slot;
            const float* hp = h1s + p * 8;
            ulonglong2 qa = *reinterpret_cast<const ulonglong2*>(hp);
            ulonglong2 qb = *reinterpret_cast<const ulonglong2*>(hp + 4);
            u64 acc = ffma2(qa.x, w2p[0],
                      ffma2(qa.y, w2p[1],
                      ffma2(qb.x, w2p[2],
                      ffma2(qb.y, w2p[3], 0ull))));
            float2 f = unpack2(acc);
            h2s[p * 8 + o] = clip1(f.x + f.y + b2o);
        }
        __syncwarp();

        // --- layer 3: v[p] = clip(h2[p] . W3 + b3), 36 values ---
        {
            int p = lane;  // 0..31
            const float* hp = h2s + p * 8;
            ulonglong2 qa = *reinterpret_cast<const ulonglong2*>(hp);
            ulonglong2 qb = *reinterpret_cast<const ulonglong2*>(hp + 4);
            u64 acc = ffma2(qa.x, w3p[0],
                      ffma2(qa.y, w3p[1],
                      ffma2(qb.x, w3p[2],
                      ffma2(qb.y, w3p[3], 0ull))));
            float2 f = unpack2(acc);
            viss[p] = clip1(f.x + f.y + b3o);
            if (lane < 4) {
                int p2 = 32 + lane;
                const float* hq = h2s + p2 * 8;
                ulonglong2 ra = *reinterpret_cast<const ulonglong2*>(hq);
                ulonglong2 rb = *reinterpret_cast<const ulonglong2*>(hq + 4);
                u64 acc2 = ffma2(ra.x, w3p[0],
                           ffma2(ra.y, w3p[1],
                           ffma2(rb.x, w3p[2],
                           ffma2(rb.y, w3p[3], 0ull))));
                float2 g = unpack2(acc2);
                viss[p2] = clip1(g.x + g.y + b3o);
            }
        }
        __syncwarp();

        // --- head layer 1: vision[37] @ E1 -> g1[16] (lanes 0..15) ---
        if (lane < 16) {
            int k = lane;
            const float* e1r = E1T + k * 38;
            u64 a0 = 0ull, a1 = 0ull, a2 = 0ull;
#pragma unroll
            for (int j = 0; j < 18; j += 3) {
                a0 = ffma2(*reinterpret_cast<const u64*>(viss + 2 * j),
                           *reinterpret_cast<const u64*>(e1r + 2 * j), a0);
                a1 = ffma2(*reinterpret_cast<const u64*>(viss + 2 * j + 2),
                           *reinterpret_cast<const u64*>(e1r + 2 * j + 2), a1);
                a2 = ffma2(*reinterpret_cast<const u64*>(viss + 2 * j + 4),
                           *reinterpret_cast<const u64*>(e1r + 2 * j + 4), a2);
            }
            a0 = ffma2(*reinterpret_cast<const u64*>(viss + 36),
                       *reinterpret_cast<const u64*>(e1r + 36), a0);
            float2 f0 = unpack2(a0), f1 = unpack2(a1), f2 = unpack2(a2);
            g1s[k] = clip1((f0.x + f0.y) + (f1.x + f1.y) + (f2.x + f2.y) + c1s[k]);
        }
        __syncwarp();

        // --- head layer 2 + output ---
        if (lane < 16) {
            int k = lane;
            const float* e2r = E2T + k * 18;
            u64 acc = 0ull;
#pragma unroll
            for (int j = 0; j < 8; j++)
                acc = ffma2(*reinterpret_cast<const u64*>(g1s + 2 * j),
                            *reinterpret_cast<const u64*>(e2r + 2 * j), acc);
            float2 f = unpack2(acc);
            float g2 = clip1(f.x + f.y + c2s[k]);
            float t = g2 * E3s[k];
            t += __shfl_xor_sync(0x0000ffffu, t, 8, 16);
            t += __shfl_xor_sync(0x0000ffffu, t, 4, 16);
            t += __shfl_xor_sync(0x0000ffffu, t, 2, 16);
            t += __shfl_xor_sync(0x0000ffffu, t, 1, 16);
            if (lane == 0) out[row] = clip1(t + c3s);
        }
    }
}

extern "C" void kernel_launch(void* const* d_in, const int* in_sizes, int n_in,
                              void* d_out, int out_size)
{
    const float* inp = (const float*)d_in[0];
    const float* W1  = (const float*)d_in[1];
    const float* b1  = (const float*)d_in[2];
    const float* W2  = (const float*)d_in[3];
    const float* b2  = (const float*)d_in[4];
    const float* W3  = (const float*)d_in[5];
    const float* b3  = (const float*)d_in[6];
    const float* E1  = (const float*)d_in[7];
    const float* c1  = (const float*)d_in[8];
    const float* E2  = (const float*)d_in[9];
    const float* c2  = (const float*)d_in[10];
    const float* E3  = (const float*)d_in[11];
    const float* c3  = (const float*)d_in[12];

    int B = in_sizes[0] / 385;

    lila_kernel<<<GRID_BLOCKS, B_THREADS>>>(inp, W1, b1, W2, b2, W3, b3,
                                            E1, c1, E2, c2, E3, c3,
                                            (float*)d_out, B);
}